// round 2
// baseline (speedup 1.0000x reference)
#include <cuda_runtime.h>
#include <cuda_bf16.h>
#include <stdint.h>

// Flash attention, B=32, LQ=LK=2048, D=128, fp32 in/out.
// Mask: one 4-byte element per position (bool promoted to int32/float32 by the
// harness); nonzero bit pattern = masked. score = (q.k)*sqrt(128) (ref bug kept).
// Precision: bf16 hi/lo split, 3-term MMA for both QK^T and PV.

namespace {

constexpr int B_   = 32;
constexpr int LQ_  = 2048;
constexpr int LK_  = 2048;
constexpr int DH   = 128;
constexpr int BR   = 128;   // query rows per CTA
constexpr int BC   = 64;    // keys per iteration
constexpr int NTH  = 256;   // 8 warps; each warp owns 16 query rows x all 64 keys
constexpr int NIT  = LK_ / BC;
constexpr int RSB  = 272;   // smem row stride bytes (128 bf16 + 8 pad)

constexpr int SM_QHI = 0;
constexpr int SM_QLO = SM_QHI + BR * RSB;
constexpr int SM_KHI = SM_QLO + BR * RSB;
constexpr int SM_KLO = SM_KHI + BC * RSB;
constexpr int SM_VHI = SM_KLO + BC * RSB;
constexpr int SM_VLO = SM_VHI + BC * RSB;
constexpr int SM_MSK = SM_VLO + BC * RSB;
constexpr int SM_TOT = SM_MSK + BR * BC;   // 147456 bytes

__device__ __forceinline__ uint32_t smem_u32(const void* p) {
    return (uint32_t)__cvta_generic_to_shared(p);
}
__device__ __forceinline__ void ldsm4(uint32_t r[4], uint32_t a) {
    asm volatile("ldmatrix.sync.aligned.m8n8.x4.shared.b16 {%0,%1,%2,%3}, [%4];"
                 : "=r"(r[0]), "=r"(r[1]), "=r"(r[2]), "=r"(r[3]) : "r"(a));
}
__device__ __forceinline__ void ldsm4t(uint32_t r[4], uint32_t a) {
    asm volatile("ldmatrix.sync.aligned.m8n8.x4.trans.shared.b16 {%0,%1,%2,%3}, [%4];"
                 : "=r"(r[0]), "=r"(r[1]), "=r"(r[2]), "=r"(r[3]) : "r"(a));
}
__device__ __forceinline__ void mma_bf16(float d[4], const uint32_t a[4], uint32_t b0, uint32_t b1) {
    asm volatile("mma.sync.aligned.m16n8k16.row.col.f32.bf16.bf16.f32 "
                 "{%0,%1,%2,%3}, {%4,%5,%6,%7}, {%8,%9}, {%0,%1,%2,%3};"
                 : "+f"(d[0]), "+f"(d[1]), "+f"(d[2]), "+f"(d[3])
                 : "r"(a[0]), "r"(a[1]), "r"(a[2]), "r"(a[3]), "r"(b0), "r"(b1));
}
__device__ __forceinline__ float ex2f(float x) {
    float y; asm("ex2.approx.f32 %0, %1;" : "=f"(y) : "f"(x)); return y;
}
__device__ __forceinline__ uint32_t bits2(__nv_bfloat162 h) {
    uint32_t u; __builtin_memcpy(&u, &h, 4); return u;
}
// hi/lo split of a float4, stored as 8 bytes hi + 8 bytes lo
__device__ __forceinline__ void split_store(float4 f, char* ph, char* pl) {
    __nv_bfloat16 h0 = __float2bfloat16_rn(f.x);
    __nv_bfloat16 h1 = __float2bfloat16_rn(f.y);
    __nv_bfloat16 h2 = __float2bfloat16_rn(f.z);
    __nv_bfloat16 h3 = __float2bfloat16_rn(f.w);
    *(__nv_bfloat162*)(ph)     = __halves2bfloat162(h0, h1);
    *(__nv_bfloat162*)(ph + 4) = __halves2bfloat162(h2, h3);
    __nv_bfloat16 l0 = __float2bfloat16_rn(f.x - __bfloat162float(h0));
    __nv_bfloat16 l1 = __float2bfloat16_rn(f.y - __bfloat162float(h1));
    __nv_bfloat16 l2 = __float2bfloat16_rn(f.z - __bfloat162float(h2));
    __nv_bfloat16 l3 = __float2bfloat16_rn(f.w - __bfloat162float(h3));
    *(__nv_bfloat162*)(pl)     = __halves2bfloat162(l0, l1);
    *(__nv_bfloat162*)(pl + 4) = __halves2bfloat162(l2, l3);
}
__device__ __forceinline__ void split_pair(float x, float y, uint32_t& hi, uint32_t& lo) {
    __nv_bfloat16 hx = __float2bfloat16_rn(x);
    __nv_bfloat16 hy = __float2bfloat16_rn(y);
    hi = bits2(__halves2bfloat162(hx, hy));
    __nv_bfloat16 lx = __float2bfloat16_rn(x - __bfloat162float(hx));
    __nv_bfloat16 ly = __float2bfloat16_rn(y - __bfloat162float(hy));
    lo = bits2(__halves2bfloat162(lx, ly));
}

__global__ void __launch_bounds__(NTH, 1)
fa_bf16x3_kernel(const float* __restrict__ qg, const float* __restrict__ kg,
                 const float* __restrict__ vg, const uint32_t* __restrict__ mg,
                 float* __restrict__ og)
{
    extern __shared__ char smem[];
    const int tid  = threadIdx.x;
    const int lane = tid & 31;
    const int warp = tid >> 5;
    const int b    = blockIdx.y;
    const int q0   = blockIdx.x * BR;

    const float K2 = 16.3222312f;   // sqrt(128) * log2(e): p = 2^(s*K2 - m)
    const float NEG = -1e30f;

    // ---- load Q tile (128x128 fp32) -> bf16 hi/lo smem ----
    {
        const float* qp = qg + ((size_t)b * LQ_ + q0) * DH;
        #pragma unroll
        for (int i = 0; i < 16; ++i) {
            int idx = tid + i * NTH;          // 4096 float4 total
            int row = idx >> 5, c4 = idx & 31;
            float4 f = *(const float4*)(qp + (size_t)row * DH + c4 * 4);
            split_store(f, smem + SM_QHI + row * RSB + c4 * 8,
                           smem + SM_QLO + row * RSB + c4 * 8);
        }
    }
    __syncthreads();

    // ---- Q fragments (persistent in registers): 8 kblocks x 4 regs, hi+lo ----
    uint32_t qa_hi[8][4], qa_lo[8][4];
    {
        uint32_t base = smem_u32(smem) + (uint32_t)((warp * 16 + (lane & 15)) * RSB + (lane >> 4) * 16);
        #pragma unroll
        for (int kb = 0; kb < 8; ++kb) {
            ldsm4(qa_hi[kb], base + SM_QHI + kb * 32);
            ldsm4(qa_lo[kb], base + SM_QLO + kb * 32);
        }
    }

    float acc[16][4];
    #pragma unroll
    for (int j = 0; j < 16; ++j) { acc[j][0]=0.f; acc[j][1]=0.f; acc[j][2]=0.f; acc[j][3]=0.f; }
    float m0r = NEG, m1r = NEG, l0r = 0.f, l1r = 0.f;

    const int r0l = warp * 16 + (lane >> 2);     // local row for C-frag half 0 (half 1 = +8)
    const uint32_t kfb = smem_u32(smem) + (uint32_t)((lane & 7) * RSB + (lane >> 3) * 16);
    const uint32_t vfb = smem_u32(smem) + (uint32_t)((lane & 15) * RSB + (lane >> 4) * 16);

    for (int kt = 0; kt < NIT; ++kt) {
        // ---- load K/V tile (64x128 fp32 each) -> bf16 hi/lo smem; mask -> packed bytes ----
        {
            const float* kp = kg + ((size_t)b * LK_ + kt * BC) * DH;
            const float* vp = vg + ((size_t)b * LK_ + kt * BC) * DH;
            #pragma unroll
            for (int i = 0; i < 8; ++i) {
                int idx = tid + i * NTH;      // 2048 float4
                int row = idx >> 5, c4 = idx & 31;
                float4 fk = *(const float4*)(kp + (size_t)row * DH + c4 * 4);
                split_store(fk, smem + SM_KHI + row * RSB + c4 * 8,
                                smem + SM_KLO + row * RSB + c4 * 8);
                float4 fv = *(const float4*)(vp + (size_t)row * DH + c4 * 4);
                split_store(fv, smem + SM_VHI + row * RSB + c4 * 8,
                                smem + SM_VLO + row * RSB + c4 * 8);
            }
            // mask: 4-byte elements (bool promoted); nonzero = masked.
            // Read uint4 (4 elems), pack to 4 bytes in smem.
            const uint32_t* mp = mg + (size_t)b * LQ_ * LK_ + (size_t)q0 * LK_ + kt * BC;
            #pragma unroll
            for (int i = 0; i < 8; ++i) {
                int idx = tid + i * NTH;      // 2048 uint4 = 128 rows x 16 segs
                int row = idx >> 4, seg = idx & 15;
                uint4 m = *(const uint4*)(mp + (size_t)row * LK_ + seg * 4);
                uint32_t packed = (m.x ? 1u : 0u) | ((m.y ? 1u : 0u) << 8) |
                                  ((m.z ? 1u : 0u) << 16) | ((m.w ? 1u : 0u) << 24);
                *(uint32_t*)(smem + SM_MSK + row * BC + seg * 4) = packed;
            }
        }
        __syncthreads();

        // ---- S = Q K^T (bf16x3), per warp: 16 rows x 64 keys ----
        float s[8][4];
        #pragma unroll
        for (int nb = 0; nb < 8; ++nb) { s[nb][0]=0.f; s[nb][1]=0.f; s[nb][2]=0.f; s[nb][3]=0.f; }
        #pragma unroll
        for (int nb = 0; nb < 8; ++nb) {
            uint32_t ka = kfb + (uint32_t)(nb * 8 * RSB);
            #pragma unroll
            for (int kp2 = 0; kp2 < 4; ++kp2) {
                uint32_t bh[4], bl[4];
                ldsm4(bh, ka + SM_KHI + kp2 * 64);
                ldsm4(bl, ka + SM_KLO + kp2 * 64);
                const int kb0 = 2 * kp2, kb1 = 2 * kp2 + 1;
                mma_bf16(s[nb], qa_hi[kb0], bh[0], bh[1]);
                mma_bf16(s[nb], qa_hi[kb0], bl[0], bl[1]);
                mma_bf16(s[nb], qa_lo[kb0], bh[0], bh[1]);
                mma_bf16(s[nb], qa_hi[kb1], bh[2], bh[3]);
                mma_bf16(s[nb], qa_hi[kb1], bl[2], bl[3]);
                mma_bf16(s[nb], qa_lo[kb1], bh[2], bh[3]);
            }
        }

        // ---- mask + scale (into log2 domain), row max ----
        float tm0 = NEG, tm1 = NEG;
        const unsigned char* mrow0 = (const unsigned char*)(smem + SM_MSK + r0l * BC);
        const unsigned char* mrow1 = mrow0 + 8 * BC;
        #pragma unroll
        for (int nb = 0; nb < 8; ++nb) {
            int c = (nb << 3) + ((lane & 3) << 1);
            s[nb][0] = mrow0[c]     ? NEG : s[nb][0] * K2;
            s[nb][1] = mrow0[c + 1] ? NEG : s[nb][1] * K2;
            s[nb][2] = mrow1[c]     ? NEG : s[nb][2] * K2;
            s[nb][3] = mrow1[c + 1] ? NEG : s[nb][3] * K2;
            tm0 = fmaxf(tm0, fmaxf(s[nb][0], s[nb][1]));
            tm1 = fmaxf(tm1, fmaxf(s[nb][2], s[nb][3]));
        }
        tm0 = fmaxf(tm0, __shfl_xor_sync(0xffffffffu, tm0, 1));
        tm0 = fmaxf(tm0, __shfl_xor_sync(0xffffffffu, tm0, 2));
        tm1 = fmaxf(tm1, __shfl_xor_sync(0xffffffffu, tm1, 1));
        tm1 = fmaxf(tm1, __shfl_xor_sync(0xffffffffu, tm1, 2));

        float mn0 = fmaxf(m0r, tm0), mn1 = fmaxf(m1r, tm1);
        float a0 = ex2f(m0r - mn0),  a1 = ex2f(m1r - mn1);   // NEG-NEG=0 -> 1 (l stays 0)
        float k0 = (mn0 > NEG) ? 1.f : 0.f;                   // kill fully-masked rows
        float k1 = (mn1 > NEG) ? 1.f : 0.f;

        float sum0 = 0.f, sum1 = 0.f;
        #pragma unroll
        for (int nb = 0; nb < 8; ++nb) {
            s[nb][0] = ex2f(s[nb][0] - mn0) * k0;
            s[nb][1] = ex2f(s[nb][1] - mn0) * k0;
            s[nb][2] = ex2f(s[nb][2] - mn1) * k1;
            s[nb][3] = ex2f(s[nb][3] - mn1) * k1;
            sum0 += s[nb][0] + s[nb][1];
            sum1 += s[nb][2] + s[nb][3];
        }
        sum0 += __shfl_xor_sync(0xffffffffu, sum0, 1);
        sum0 += __shfl_xor_sync(0xffffffffu, sum0, 2);
        sum1 += __shfl_xor_sync(0xffffffffu, sum1, 1);
        sum1 += __shfl_xor_sync(0xffffffffu, sum1, 2);
        l0r = l0r * a0 + sum0;
        l1r = l1r * a1 + sum1;
        m0r = mn0; m1r = mn1;

        #pragma unroll
        for (int j = 0; j < 16; ++j) {
            acc[j][0] *= a0; acc[j][1] *= a0; acc[j][2] *= a1; acc[j][3] *= a1;
        }

        // ---- O += P V (bf16x3); P C-frags reused as A-frags in registers ----
        #pragma unroll
        for (int kb = 0; kb < 4; ++kb) {
            uint32_t ah[4], al[4];
            split_pair(s[2*kb][0],   s[2*kb][1],   ah[0], al[0]);
            split_pair(s[2*kb][2],   s[2*kb][3],   ah[1], al[1]);
            split_pair(s[2*kb+1][0], s[2*kb+1][1], ah[2], al[2]);
            split_pair(s[2*kb+1][2], s[2*kb+1][3], ah[3], al[3]);
            uint32_t va = vfb + (uint32_t)(kb * 16 * RSB);
            #pragma unroll
            for (int jp = 0; jp < 8; ++jp) {
                uint32_t bh[4], bl[4];
                ldsm4t(bh, va + SM_VHI + jp * 32);
                ldsm4t(bl, va + SM_VLO + jp * 32);
                mma_bf16(acc[2*jp],   ah, bh[0], bh[1]);
                mma_bf16(acc[2*jp],   ah, bl[0], bl[1]);
                mma_bf16(acc[2*jp],   al, bh[0], bh[1]);
                mma_bf16(acc[2*jp+1], ah, bh[2], bh[3]);
                mma_bf16(acc[2*jp+1], ah, bl[2], bl[3]);
                mma_bf16(acc[2*jp+1], al, bh[2], bh[3]);
            }
        }
        __syncthreads();
    }

    // ---- epilogue: normalize (fully-masked rows -> 0) and store ----
    float inv0 = (l0r > 0.f) ? (1.0f / l0r) : 0.f;
    float inv1 = (l1r > 0.f) ? (1.0f / l1r) : 0.f;
    const size_t gr0 = (size_t)b * LQ_ + q0 + r0l;
    const size_t gr1 = gr0 + 8;
    #pragma unroll
    for (int j = 0; j < 16; ++j) {
        int c = (j << 3) + ((lane & 3) << 1);
        float2 o0 = make_float2(acc[j][0] * inv0, acc[j][1] * inv0);
        float2 o1 = make_float2(acc[j][2] * inv1, acc[j][3] * inv1);
        *(float2*)(og + gr0 * DH + c) = o0;
        *(float2*)(og + gr1 * DH + c) = o1;
    }
}

} // namespace

extern "C" void kernel_launch(void* const* d_in, const int* in_sizes, int n_in,
                              void* d_out, int out_size) {
    const float* q = (const float*)d_in[0];
    const float* k = (const float*)d_in[1];
    const float* v = (const float*)d_in[2];
    const uint32_t* mask = (const uint32_t*)d_in[3];
    float* out = (float*)d_out;
    (void)in_sizes; (void)n_in; (void)out_size;

    cudaFuncSetAttribute(fa_bf16x3_kernel, cudaFuncAttributeMaxDynamicSharedMemorySize, SM_TOT);
    dim3 grid(LQ_ / BR, B_);
    fa_bf16x3_kernel<<<grid, NTH, SM_TOT>>>(q, k, v, mask, out);
}